// round 1
// baseline (speedup 1.0000x reference)
#include <cuda_runtime.h>

// ---------------- scratch (static device globals; no allocation) ----------------
__device__ float g_h1[16 * 64 * 128 * 128];   // conv1 out, 64 MB
__device__ float g_h2[16 * 128 * 64 * 64];    // conv2 out, 32 MB
__device__ float g_h3[16 * 128 * 64 * 64];    // conv3 out / residual accum, 32 MB
__device__ float g_t [16 * 32 * 64 * 64];     // res-block intermediate, 8 MB
__device__ float g_z [16 * 4096 * 4];         // pre-VQ latents, position-major [pos][4]

// ---------------- conv1: [16,1,256,256] -> relu -> [16,64,128,128], k4 s2 p1 ----
__global__ void k_conv1(const float* __restrict__ x, const float* __restrict__ w,
                        const float* __restrict__ b) {
    // grid (oy=128, b=16), block 128 (ox)
    const int oy = blockIdx.x, bb = blockIdx.y, ox = threadIdx.x;
    __shared__ float sw[64 * 16];
    __shared__ float sb[64];
    for (int i = threadIdx.x; i < 64 * 16; i += 128) sw[i] = w[i];
    if (threadIdx.x < 64) sb[threadIdx.x] = b[threadIdx.x];
    __syncthreads();

    const float* xb = x + bb * 256 * 256;
    float iv[16];
#pragma unroll
    for (int kh = 0; kh < 4; kh++) {
        const int iy = 2 * oy - 1 + kh;
#pragma unroll
        for (int kw = 0; kw < 4; kw++) {
            const int ix = 2 * ox - 1 + kw;
            iv[kh * 4 + kw] = (iy >= 0 && iy < 256 && ix >= 0 && ix < 256)
                                  ? xb[iy * 256 + ix] : 0.f;
        }
    }
    float* ob = g_h1 + bb * 64 * 16384 + oy * 128 + ox;
    for (int oc = 0; oc < 64; oc++) {
        float a = sb[oc];
#pragma unroll
        for (int t = 0; t < 16; t++) a += iv[t] * sw[oc * 16 + t];
        ob[oc * 16384] = fmaxf(a, 0.f);
    }
}

// ---------------- conv2: [16,64,128,128] -> relu -> [16,128,64,64], k4 s2 p1 ----
__global__ void k_conv2(const float* __restrict__ w, const float* __restrict__ b) {
    // grid (oy=64, ocg=8, b=16), block 64 (ox); 16 oc per thread
    const int oy = blockIdx.x, ocb = blockIdx.y * 16, bb = blockIdx.z, tx = threadIdx.x;
    __shared__ float  s_in[8][4][132];     // [ci][kh][ix+1], 130 used
    __shared__ float4 s_w [16][8][4];      // [o][ci][kh] = 4 kw taps

    float acc[16];
#pragma unroll
    for (int o = 0; o < 16; o++) acc[o] = b[ocb + o];

    const float* inb = g_h1 + bb * 64 * 16384;
    for (int cb = 0; cb < 64; cb += 8) {
        __syncthreads();
        for (int i = tx; i < 8 * 4 * 130; i += 64) {
            const int ci = i / 520, r = i % 520, kh = r / 130, xx = r % 130;
            const int iy = 2 * oy - 1 + kh, ix = xx - 1;
            float v = 0.f;
            if (iy >= 0 && iy < 128 && ix >= 0 && ix < 128)
                v = inb[(cb + ci) * 16384 + iy * 128 + ix];
            s_in[ci][kh][xx] = v;
        }
        for (int i = tx; i < 16 * 8 * 16; i += 64) {
            const int o = i >> 7, r = i & 127, ci = r >> 4, t = r & 15;
            ((float*)&s_w[o][ci][0])[t] = w[(ocb + o) * 1024 + (cb + ci) * 16 + t];
        }
        __syncthreads();
#pragma unroll 2
        for (int ci = 0; ci < 8; ci++) {
#pragma unroll
            for (int kh = 0; kh < 4; kh++) {
                const float r0 = s_in[ci][kh][2 * tx + 0];
                const float r1 = s_in[ci][kh][2 * tx + 1];
                const float r2 = s_in[ci][kh][2 * tx + 2];
                const float r3 = s_in[ci][kh][2 * tx + 3];
#pragma unroll
                for (int o = 0; o < 16; o++) {
                    const float4 wv = s_w[o][ci][kh];
                    acc[o] += r0 * wv.x + r1 * wv.y + r2 * wv.z + r3 * wv.w;
                }
            }
        }
    }
    float* ob = g_h2 + (bb * 128 + ocb) * 4096 + oy * 64 + tx;
#pragma unroll
    for (int o = 0; o < 16; o++) ob[o * 4096] = fmaxf(acc[o], 0.f);
}

// ---------------- generic 3x3 s1 p1 conv on 64x64, CIN=128, 16 oc per block ----
template <bool RELU_IN>
__global__ void k_conv3x3(const float* __restrict__ in, const float* __restrict__ w,
                          const float* __restrict__ b, float* __restrict__ out,
                          int COUT) {
    // grid (oy=64, ocg=COUT/16, b=16), block 64 (ox)
    const int oy = blockIdx.x, ocb = blockIdx.y * 16, bb = blockIdx.z, tx = threadIdx.x;
    __shared__ float  s_in[8][3][68];      // [ci][kh][ix+1], 66 used
    __shared__ float4 s_w [16][8][3];      // [o][ci][kh] = (w0,w1,w2, pad)

    float acc[16];
#pragma unroll
    for (int o = 0; o < 16; o++) acc[o] = b[ocb + o];

    const float* inb = in + bb * 128 * 4096;
    for (int cb = 0; cb < 128; cb += 8) {
        __syncthreads();
        for (int i = tx; i < 8 * 3 * 66; i += 64) {
            const int ci = i / 198, r = i % 198, kh = r / 66, xx = r % 66;
            const int iy = oy - 1 + kh, ix = xx - 1;
            float v = 0.f;
            if (iy >= 0 && iy < 64 && ix >= 0 && ix < 64)
                v = inb[(cb + ci) * 4096 + iy * 64 + ix];
            if (RELU_IN) v = fmaxf(v, 0.f);
            s_in[ci][kh][xx] = v;
        }
        for (int i = tx; i < 16 * 8 * 9; i += 64) {
            const int o = i / 72, r = i % 72, ci = r / 9, t = r % 9;
            ((float*)&s_w[o][ci][t / 3])[t % 3] = w[(ocb + o) * 128 * 9 + (cb + ci) * 9 + t];
        }
        __syncthreads();
#pragma unroll 2
        for (int ci = 0; ci < 8; ci++) {
#pragma unroll
            for (int kh = 0; kh < 3; kh++) {
                const float r0 = s_in[ci][kh][tx + 0];
                const float r1 = s_in[ci][kh][tx + 1];
                const float r2 = s_in[ci][kh][tx + 2];
#pragma unroll
                for (int o = 0; o < 16; o++) {
                    const float4 wv = s_w[o][ci][kh];
                    acc[o] += r0 * wv.x + r1 * wv.y + r2 * wv.z;
                }
            }
        }
    }
    float* ob = out + (bb * COUT + ocb) * 4096 + oy * 64 + tx;
#pragma unroll
    for (int o = 0; o < 16; o++) ob[o * 4096] = acc[o];
}

// ------- residual 1x1: h3 += bias + W(32->64oc chunk) * relu(t) -----------------
__global__ void k_res1x1_add(const float* __restrict__ w, const float* __restrict__ b) {
    // grid (xyg=64, ocg=2, b=16), block 64 (xy); 64 oc per thread
    const int xy0 = blockIdx.x * 64, ocb = blockIdx.y * 64, bb = blockIdx.z, tx = threadIdx.x;
    __shared__ float  s_t[32][64];
    __shared__ float4 s_w4[64][8];         // [o][ci/4]

    const float* tb = g_t + bb * 32 * 4096 + xy0;
    for (int i = tx; i < 32 * 64; i += 64) {
        const int ci = i / 64, xx = i % 64;
        s_t[ci][xx] = fmaxf(tb[ci * 4096 + xx], 0.f);
    }
    for (int i = tx; i < 64 * 32; i += 64) {
        const int o = i / 32, ci = i % 32;
        ((float*)&s_w4[o][0])[ci] = w[(ocb + o) * 32 + ci];
    }
    __syncthreads();

    float acc[64];
#pragma unroll
    for (int o = 0; o < 64; o++) acc[o] = b[ocb + o];
    for (int cq = 0; cq < 8; cq++) {
        const float t0 = s_t[cq * 4 + 0][tx];
        const float t1 = s_t[cq * 4 + 1][tx];
        const float t2 = s_t[cq * 4 + 2][tx];
        const float t3 = s_t[cq * 4 + 3][tx];
#pragma unroll
        for (int o = 0; o < 64; o++) {
            const float4 wv = s_w4[o][cq];
            acc[o] += t0 * wv.x + t1 * wv.y + t2 * wv.z + t3 * wv.w;
        }
    }
    float* hb = g_h3 + (bb * 128 + ocb) * 4096 + xy0 + tx;
#pragma unroll
    for (int o = 0; o < 64; o++) hb[o * 4096] += acc[o];
}

// ------- pre-VQ 1x1: z[pos][4] = W(128->4) * relu(h3) + bias --------------------
__global__ void k_z(const float* __restrict__ w, const float* __restrict__ b) {
    // grid (xyg=64, b=16), block 64
    const int xy0 = blockIdx.x * 64, bb = blockIdx.y, tx = threadIdx.x;
    __shared__ float s_h[128][64];
    __shared__ float s_w[4][128];

    const float* hb = g_h3 + bb * 128 * 4096 + xy0;
    for (int i = tx; i < 128 * 64; i += 64) {
        const int ci = i / 64, xx = i % 64;
        s_h[ci][xx] = fmaxf(hb[ci * 4096 + xx], 0.f);
    }
    for (int i = tx; i < 512; i += 64) s_w[i / 128][i % 128] = w[i];
    __syncthreads();

    float a0 = b[0], a1 = b[1], a2 = b[2], a3 = b[3];
#pragma unroll 4
    for (int ci = 0; ci < 128; ci++) {
        const float hv = s_h[ci][tx];
        a0 += hv * s_w[0][ci];
        a1 += hv * s_w[1][ci];
        a2 += hv * s_w[2][ci];
        a3 += hv * s_w[3][ci];
    }
    ((float4*)g_z)[bb * 4096 + xy0 + tx] = make_float4(a0, a1, a2, a3);
}

// ------- cosine VQ: argmax_k <z, e_k/||e_k||>, gather codebook ------------------
// Note: reference normalizes z too, but that is a positive per-position scalar
// and cannot change the argmax -> skipped exactly.
__global__ void k_vq(const float* __restrict__ cb, float* __restrict__ out) {
    // grid (posg=16, b=16), block 256
    const int bb = blockIdx.y;
    const int pos = blockIdx.x * 256 + threadIdx.x;
    __shared__ float4 s_en[2048];
    for (int k = threadIdx.x; k < 2048; k += 256) {
        const float4 c = ((const float4*)cb)[k];
        const float n = sqrtf(c.x * c.x + c.y * c.y + c.z * c.z + c.w * c.w);
        const float inv = 1.f / (n + 1e-12f);
        s_en[k] = make_float4(c.x * inv, c.y * inv, c.z * inv, c.w * inv);
    }
    __syncthreads();

    const float4 z = ((const float4*)g_z)[bb * 4096 + pos];
    float best = -1e30f;
    int bi = 0;
#pragma unroll 8
    for (int k = 0; k < 2048; k++) {
        const float4 e = s_en[k];
        const float s = z.x * e.x + z.y * e.y + z.z * e.z + z.w * e.w;
        if (s > best) { best = s; bi = k; }   // strict > keeps first max (JAX semantics)
    }
    const float4 q = ((const float4*)cb)[bi];
    float* ob = out + bb * 4 * 4096 + pos;
    ob[0]        = q.x;
    ob[4096]     = q.y;
    ob[2 * 4096] = q.z;
    ob[3 * 4096] = q.w;
}

// --------------------------------- launcher -------------------------------------
extern "C" void kernel_launch(void* const* d_in, const int* in_sizes, int n_in,
                              void* d_out, int out_size) {
    const float* cond  = (const float*)d_in[0];
    const float* w1    = (const float*)d_in[1];
    const float* b1    = (const float*)d_in[2];
    const float* w2    = (const float*)d_in[3];
    const float* b2    = (const float*)d_in[4];
    const float* w3    = (const float*)d_in[5];
    const float* b3    = (const float*)d_in[6];
    const float* r1w1  = (const float*)d_in[7];
    const float* r1b1  = (const float*)d_in[8];
    const float* r1w2  = (const float*)d_in[9];
    const float* r1b2  = (const float*)d_in[10];
    const float* r2w1  = (const float*)d_in[11];
    const float* r2b1  = (const float*)d_in[12];
    const float* r2w2  = (const float*)d_in[13];
    const float* r2b2  = (const float*)d_in[14];
    const float* wpre  = (const float*)d_in[15];
    const float* bpre  = (const float*)d_in[16];
    const float* cbk   = (const float*)d_in[17];

    float *h2p, *h3p, *tp;
    cudaGetSymbolAddress((void**)&h2p, g_h2);
    cudaGetSymbolAddress((void**)&h3p, g_h3);
    cudaGetSymbolAddress((void**)&tp,  g_t);

    k_conv1<<<dim3(128, 16), 128>>>(cond, w1, b1);
    k_conv2<<<dim3(64, 8, 16), 64>>>(w2, b2);
    k_conv3x3<false><<<dim3(64, 8, 16), 64>>>(h2p, w3, b3, h3p, 128);

    k_conv3x3<true><<<dim3(64, 2, 16), 64>>>(h3p, r1w1, r1b1, tp, 32);
    k_res1x1_add<<<dim3(64, 2, 16), 64>>>(r1w2, r1b2);

    k_conv3x3<true><<<dim3(64, 2, 16), 64>>>(h3p, r2w1, r2b1, tp, 32);
    k_res1x1_add<<<dim3(64, 2, 16), 64>>>(r2w2, r2b2);

    k_z<<<dim3(64, 16), 64>>>(wpre, bpre);
    k_vq<<<dim3(16, 16), 256>>>(cbk, (float*)d_out);
}

// round 2
// speedup vs baseline: 1.4160x; 1.4160x over previous
#include <cuda_runtime.h>

// ---------------- scratch (static device globals; no allocation) ----------------
__device__ float g_h1[16 * 64 * 128 * 128];   // conv1 out, 64 MB
__device__ float g_h2[16 * 128 * 64 * 64];    // conv2 out, 32 MB
__device__ float g_h3[16 * 128 * 64 * 64];    // conv3 out / residual accum, 32 MB
__device__ float g_t [16 * 32 * 64 * 64];     // res-block intermediate, 8 MB
__device__ float g_z [16 * 4096 * 4];         // pre-VQ latents, position-major [pos][4]

// ---------------- conv1: [16,1,256,256] -> relu -> [16,64,128,128], k4 s2 p1 ----
__global__ void k_conv1(const float* __restrict__ x, const float* __restrict__ w,
                        const float* __restrict__ b) {
    // grid (oy=128, b=16), block 128 (ox)
    const int oy = blockIdx.x, bb = blockIdx.y, ox = threadIdx.x;
    __shared__ float sw[64 * 16];
    __shared__ float sb[64];
    for (int i = threadIdx.x; i < 64 * 16; i += 128) sw[i] = w[i];
    if (threadIdx.x < 64) sb[threadIdx.x] = b[threadIdx.x];
    __syncthreads();

    const float* xb = x + bb * 256 * 256;
    float iv[16];
#pragma unroll
    for (int kh = 0; kh < 4; kh++) {
        const int iy = 2 * oy - 1 + kh;
#pragma unroll
        for (int kw = 0; kw < 4; kw++) {
            const int ix = 2 * ox - 1 + kw;
            iv[kh * 4 + kw] = (iy >= 0 && iy < 256 && ix >= 0 && ix < 256)
                                  ? xb[iy * 256 + ix] : 0.f;
        }
    }
    float* ob = g_h1 + bb * 64 * 16384 + oy * 128 + ox;
    for (int oc = 0; oc < 64; oc++) {
        float a = sb[oc];
#pragma unroll
        for (int t = 0; t < 16; t++) a += iv[t] * sw[oc * 16 + t];
        ob[oc * 16384] = fmaxf(a, 0.f);
    }
}

// ---------------- conv2: [16,64,128,128] -> relu -> [16,128,64,64], k4 s2 p1 ----
// block 64 = 16 x-groups (4 px each) x 4 rows; 16 oc x 4 px register tile
__global__ __launch_bounds__(64) void k_conv2(const float* __restrict__ w,
                                              const float* __restrict__ b) {
    // grid (oyt=16, ocg=8, bb=16)
    const int oy0 = blockIdx.x * 4, ocb = blockIdx.y * 16, bb = blockIdx.z;
    const int tid = threadIdx.x, txx = tid & 15, tyy = tid >> 4;

    __shared__ float  s_in[4][10][132];    // [ci][iy-(2*oy0-1)][ix+1], 130 cols used
    __shared__ float4 s_w [16][4][4];      // [o][ci][kh] = 4 kw taps

    float4 acc[16];
#pragma unroll
    for (int o = 0; o < 16; o++) {
        const float bv = b[ocb + o];
        acc[o] = make_float4(bv, bv, bv, bv);
    }

    const float* inb = g_h1 + bb * 64 * 16384;
    for (int cb = 0; cb < 64; cb += 4) {
        __syncthreads();
        // stage inputs: 4 ci x 10 rows x 130 cols
        for (int i = tid; i < 4 * 10 * 130; i += 64) {
            const int ci = i / 1300, r = i % 1300, row = r / 130, xx = r % 130;
            const int iy = 2 * oy0 - 1 + row, ix = xx - 1;
            float v = 0.f;
            if (iy >= 0 && iy < 128 && ix >= 0 && ix < 128)
                v = inb[(cb + ci) * 16384 + iy * 128 + ix];
            s_in[ci][row][xx] = v;
        }
        // stage weights: [o][ci][kh] float4 over kw
        for (int i = tid; i < 16 * 4 * 4; i += 64) {
            const int o = i >> 4, ci = (i >> 2) & 3, kh = i & 3;
            s_w[o][ci][kh] = ((const float4*)w)[((ocb + o) * 64 + cb + ci) * 4 + kh];
        }
        __syncthreads();

        for (int ci = 0; ci < 4; ci++) {
#pragma unroll
            for (int kh = 0; kh < 4; kh++) {
                const float* rp = &s_in[ci][2 * tyy + kh][8 * txx];
                const float4 A = *(const float4*)rp;
                const float4 B = *(const float4*)(rp + 4);
                const float2 C = *(const float2*)(rp + 8);
#pragma unroll
                for (int o = 0; o < 16; o++) {
                    const float4 wv = s_w[o][ci][kh];
                    acc[o].x += A.x * wv.x + A.y * wv.y + A.z * wv.z + A.w * wv.w;
                    acc[o].y += A.z * wv.x + A.w * wv.y + B.x * wv.z + B.y * wv.w;
                    acc[o].z += B.x * wv.x + B.y * wv.y + B.z * wv.z + B.w * wv.w;
                    acc[o].w += B.z * wv.x + B.w * wv.y + C.x * wv.z + C.y * wv.w;
                }
            }
        }
    }
    float* ob = g_h2 + (bb * 128 + ocb) * 4096 + (oy0 + tyy) * 64 + 4 * txx;
#pragma unroll
    for (int o = 0; o < 16; o++) {
        float4 v = acc[o];
        v.x = fmaxf(v.x, 0.f); v.y = fmaxf(v.y, 0.f);
        v.z = fmaxf(v.z, 0.f); v.w = fmaxf(v.w, 0.f);
        *(float4*)(ob + o * 4096) = v;
    }
}

// ---------------- generic 3x3 s1 p1 conv on 64x64, CIN=128 ----------------------
// block 16*R threads = 16 x-groups (4 px) x R rows; 16 oc x 4 px register tile
template <bool RELU_IN, int R>
__global__ __launch_bounds__(16 * R) void k_conv3x3(const float* __restrict__ in,
                                                    const float* __restrict__ w,
                                                    const float* __restrict__ b,
                                                    float* __restrict__ out,
                                                    int COUT) {
    // grid (64/R, COUT/16, 16)
    const int oy0 = blockIdx.x * R, ocb = blockIdx.y * 16, bb = blockIdx.z;
    const int tid = threadIdx.x, txx = tid & 15, tyy = tid >> 4;
    const int NT = 16 * R;

    __shared__ float  s_in[8][R + 2][68];  // [ci][iy-(oy0-1)][ix+1], 66 cols used
    __shared__ float4 s_w [16][8][3];      // [o][ci][kh] = (w0,w1,w2,pad)

    float4 acc[16];
#pragma unroll
    for (int o = 0; o < 16; o++) {
        const float bv = b[ocb + o];
        acc[o] = make_float4(bv, bv, bv, bv);
    }

    const float* inb = in + bb * 128 * 4096;
    for (int cb = 0; cb < 128; cb += 8) {
        __syncthreads();
        // stage inputs: 8 ci x (R+2) rows x 66 cols
        for (int i = tid; i < 8 * (R + 2) * 66; i += NT) {
            const int ci = i / ((R + 2) * 66), r = i % ((R + 2) * 66);
            const int row = r / 66, xx = r % 66;
            const int iy = oy0 - 1 + row, ix = xx - 1;
            float v = 0.f;
            if (iy >= 0 && iy < 64 && ix >= 0 && ix < 64)
                v = inb[(cb + ci) * 4096 + iy * 64 + ix];
            if (RELU_IN) v = fmaxf(v, 0.f);
            s_in[ci][row][xx] = v;
        }
        // stage weights
        for (int i = tid; i < 16 * 8 * 9; i += NT) {
            const int o = i / 72, r = i % 72, ci = r / 9, t = r % 9;
            ((float*)&s_w[o][ci][t / 3])[t % 3] = w[(ocb + o) * 128 * 9 + (cb + ci) * 9 + t];
        }
        __syncthreads();

        for (int ci = 0; ci < 8; ci++) {
#pragma unroll
            for (int kh = 0; kh < 3; kh++) {
                const float* rp = &s_in[ci][tyy + kh][4 * txx];
                const float4 A = *(const float4*)rp;
                const float2 C = *(const float2*)(rp + 4);
#pragma unroll
                for (int o = 0; o < 16; o++) {
                    const float4 wv = s_w[o][ci][kh];
                    acc[o].x += A.x * wv.x + A.y * wv.y + A.z * wv.z;
                    acc[o].y += A.y * wv.x + A.z * wv.y + A.w * wv.z;
                    acc[o].z += A.z * wv.x + A.w * wv.y + C.x * wv.z;
                    acc[o].w += A.w * wv.x + C.x * wv.y + C.y * wv.z;
                }
            }
        }
    }
    float* ob = out + (bb * COUT + ocb) * 4096 + (oy0 + tyy) * 64 + 4 * txx;
#pragma unroll
    for (int o = 0; o < 16; o++) *(float4*)(ob + o * 4096) = acc[o];
}

// ------- residual 1x1: h3 += bias + W(32->64oc chunk) * relu(t) -----------------
__global__ void k_res1x1_add(const float* __restrict__ w, const float* __restrict__ b) {
    // grid (xyg=64, ocg=2, b=16), block 64 (xy); 64 oc per thread
    const int xy0 = blockIdx.x * 64, ocb = blockIdx.y * 64, bb = blockIdx.z, tx = threadIdx.x;
    __shared__ float  s_t[32][64];
    __shared__ float4 s_w4[64][8];         // [o][ci/4]

    const float* tb = g_t + bb * 32 * 4096 + xy0;
    for (int i = tx; i < 32 * 64; i += 64) {
        const int ci = i / 64, xx = i % 64;
        s_t[ci][xx] = fmaxf(tb[ci * 4096 + xx], 0.f);
    }
    for (int i = tx; i < 64 * 32; i += 64) {
        const int o = i / 32, ci = i % 32;
        ((float*)&s_w4[o][0])[ci] = w[(ocb + o) * 32 + ci];
    }
    __syncthreads();

    float acc[64];
#pragma unroll
    for (int o = 0; o < 64; o++) acc[o] = b[ocb + o];
    for (int cq = 0; cq < 8; cq++) {
        const float t0 = s_t[cq * 4 + 0][tx];
        const float t1 = s_t[cq * 4 + 1][tx];
        const float t2 = s_t[cq * 4 + 2][tx];
        const float t3 = s_t[cq * 4 + 3][tx];
#pragma unroll
        for (int o = 0; o < 64; o++) {
            const float4 wv = s_w4[o][cq];
            acc[o] += t0 * wv.x + t1 * wv.y + t2 * wv.z + t3 * wv.w;
        }
    }
    float* hb = g_h3 + (bb * 128 + ocb) * 4096 + xy0 + tx;
#pragma unroll
    for (int o = 0; o < 64; o++) hb[o * 4096] += acc[o];
}

// ------- pre-VQ 1x1: z[pos][4] = W(128->4) * relu(h3) + bias --------------------
__global__ void k_z(const float* __restrict__ w, const float* __restrict__ b) {
    // grid (xyg=64, b=16), block 64
    const int xy0 = blockIdx.x * 64, bb = blockIdx.y, tx = threadIdx.x;
    __shared__ float s_h[128][64];
    __shared__ float s_w[4][128];

    const float* hb = g_h3 + bb * 128 * 4096 + xy0;
    for (int i = tx; i < 128 * 64; i += 64) {
        const int ci = i / 64, xx = i % 64;
        s_h[ci][xx] = fmaxf(hb[ci * 4096 + xx], 0.f);
    }
    for (int i = tx; i < 512; i += 64) s_w[i / 128][i % 128] = w[i];
    __syncthreads();

    float a0 = b[0], a1 = b[1], a2 = b[2], a3 = b[3];
#pragma unroll 4
    for (int ci = 0; ci < 128; ci++) {
        const float hv = s_h[ci][tx];
        a0 += hv * s_w[0][ci];
        a1 += hv * s_w[1][ci];
        a2 += hv * s_w[2][ci];
        a3 += hv * s_w[3][ci];
    }
    ((float4*)g_z)[bb * 4096 + xy0 + tx] = make_float4(a0, a1, a2, a3);
}

// ------- cosine VQ: argmax_k <z, e_k/||e_k||>, gather codebook ------------------
// Reference also normalizes z, but that positive per-position scalar cannot
// change the argmax -> skipped exactly. 4 positions per thread.
__global__ void k_vq(const float* __restrict__ cb, float* __restrict__ out) {
    // grid (posg=4, b=16), block 256; each thread: 4 consecutive positions
    const int bb = blockIdx.y;
    const int p0 = (blockIdx.x * 256 + threadIdx.x) * 4;
    __shared__ float4 s_en[2048];
    for (int k = threadIdx.x; k < 2048; k += 256) {
        const float4 c = ((const float4*)cb)[k];
        const float n = sqrtf(c.x * c.x + c.y * c.y + c.z * c.z + c.w * c.w);
        const float inv = 1.f / (n + 1e-12f);
        s_en[k] = make_float4(c.x * inv, c.y * inv, c.z * inv, c.w * inv);
    }
    __syncthreads();

    float4 z[4];
#pragma unroll
    for (int q = 0; q < 4; q++) z[q] = ((const float4*)g_z)[bb * 4096 + p0 + q];

    float best[4] = {-1e30f, -1e30f, -1e30f, -1e30f};
    int bi[4] = {0, 0, 0, 0};
#pragma unroll 4
    for (int k = 0; k < 2048; k++) {
        const float4 e = s_en[k];
#pragma unroll
        for (int q = 0; q < 4; q++) {
            const float s = z[q].x * e.x + z[q].y * e.y + z[q].z * e.z + z[q].w * e.w;
            if (s > best[q]) { best[q] = s; bi[q] = k; }  // strict >: first max (JAX)
        }
    }
    float4 qv[4];
#pragma unroll
    for (int q = 0; q < 4; q++) qv[q] = ((const float4*)cb)[bi[q]];

    float* ob = out + bb * 4 * 4096 + p0;
    *(float4*)(ob)            = make_float4(qv[0].x, qv[1].x, qv[2].x, qv[3].x);
    *(float4*)(ob + 4096)     = make_float4(qv[0].y, qv[1].y, qv[2].y, qv[3].y);
    *(float4*)(ob + 2 * 4096) = make_float4(qv[0].z, qv[1].z, qv[2].z, qv[3].z);
    *(float4*)(ob + 3 * 4096) = make_float4(qv[0].w, qv[1].w, qv[2].w, qv[3].w);
}

// --------------------------------- launcher -------------------------------------
extern "C" void kernel_launch(void* const* d_in, const int* in_sizes, int n_in,
                              void* d_out, int out_size) {
    const float* cond  = (const float*)d_in[0];
    const float* w1    = (const float*)d_in[1];
    const float* b1    = (const float*)d_in[2];
    const float* w2    = (const float*)d_in[3];
    const float* b2    = (const float*)d_in[4];
    const float* w3    = (const float*)d_in[5];
    const float* b3    = (const float*)d_in[6];
    const float* r1w1  = (const float*)d_in[7];
    const float* r1b1  = (const float*)d_in[8];
    const float* r1w2  = (const float*)d_in[9];
    const float* r1b2  = (const float*)d_in[10];
    const float* r2w1  = (const float*)d_in[11];
    const float* r2b1  = (const float*)d_in[12];
    const float* r2w2  = (const float*)d_in[13];
    const float* r2b2  = (const float*)d_in[14];
    const float* wpre  = (const float*)d_in[15];
    const float* bpre  = (const float*)d_in[16];
    const float* cbk   = (const float*)d_in[17];

    float *h2p, *h3p, *tp;
    cudaGetSymbolAddress((void**)&h2p, g_h2);
    cudaGetSymbolAddress((void**)&h3p, g_h3);
    cudaGetSymbolAddress((void**)&tp,  g_t);

    k_conv1<<<dim3(128, 16), 128>>>(cond, w1, b1);
    k_conv2<<<dim3(16, 8, 16), 64>>>(w2, b2);
    k_conv3x3<false, 8><<<dim3(8, 8, 16), 128>>>(h2p, w3, b3, h3p, 128);

    k_conv3x3<true, 4><<<dim3(16, 2, 16), 64>>>(h3p, r1w1, r1b1, tp, 32);
    k_res1x1_add<<<dim3(64, 2, 16), 64>>>(r1w2, r1b2);

    k_conv3x3<true, 4><<<dim3(16, 2, 16), 64>>>(h3p, r2w1, r2b1, tp, 32);
    k_res1x1_add<<<dim3(64, 2, 16), 64>>>(r2w2, r2b2);

    k_z<<<dim3(64, 16), 64>>>(wpre, bpre);
    k_vq<<<dim3(4, 16), 256>>>(cbk, (float*)d_out);
}

// round 3
// speedup vs baseline: 1.7650x; 1.2464x over previous
#include <cuda_runtime.h>
#include <cuda_pipeline.h>

// ---------------- scratch (static device globals; no allocation) ----------------
__device__ float  g_h1 [16 * 64 * 128 * 128];   // conv1 out (relu'd), 64 MB
__device__ float  g_h2 [16 * 128 * 64 * 64];    // conv2 out (relu'd), 32 MB
__device__ float  g_h3 [16 * 128 * 64 * 64];    // conv3/residual accum (raw), 32 MB
__device__ float  g_h3r[16 * 128 * 64 * 64];    // relu(h3), kept in sync, 32 MB
__device__ float  g_t  [2 * 16 * 32 * 64 * 64]; // res 3x3 partial sums (2 ci-halves)
__device__ float  g_z  [16 * 4096 * 4];         // pre-VQ latents [pos][4]
__device__ float4 g_w3p [128 * 128 * 3];        // padded 3x3 weights (w,x,y,z=0)
__device__ float4 g_wr1p[32 * 128 * 3];
__device__ float4 g_wr2p[32 * 128 * 3];

// ------------- pad 3x3 weights into float4 [oc][ci][kh] = (w0,w1,w2,0) ----------
__global__ void k_padw(const float* __restrict__ w3, const float* __restrict__ r1,
                       const float* __restrict__ r2) {
    const int i = blockIdx.x * 256 + threadIdx.x;
    const float* src; float4* dst; int base;
    if (i < 49152)      { src = w3; dst = g_w3p;  base = i; }
    else if (i < 61440) { src = r1; dst = g_wr1p; base = i - 49152; }
    else if (i < 73728) { src = r2; dst = g_wr2p; base = i - 61440; }
    else return;
    dst[base] = make_float4(src[base * 3], src[base * 3 + 1], src[base * 3 + 2], 0.f);
}

// ---------------- conv1: [16,1,256,256] -> relu -> [16,64,128,128], k4 s2 p1 ----
__global__ void k_conv1(const float* __restrict__ x, const float* __restrict__ w,
                        const float* __restrict__ b) {
    const int oy = blockIdx.x, bb = blockIdx.y, ox = threadIdx.x;
    __shared__ float sw[64 * 16];
    __shared__ float sb[64];
    for (int i = threadIdx.x; i < 64 * 16; i += 128) sw[i] = w[i];
    if (threadIdx.x < 64) sb[threadIdx.x] = b[threadIdx.x];
    __syncthreads();

    const float* xb = x + bb * 256 * 256;
    float iv[16];
#pragma unroll
    for (int kh = 0; kh < 4; kh++) {
        const int iy = 2 * oy - 1 + kh;
#pragma unroll
        for (int kw = 0; kw < 4; kw++) {
            const int ix = 2 * ox - 1 + kw;
            iv[kh * 4 + kw] = (iy >= 0 && iy < 256 && ix >= 0 && ix < 256)
                                  ? xb[iy * 256 + ix] : 0.f;
        }
    }
    float* ob = g_h1 + bb * 64 * 16384 + oy * 128 + ox;
    for (int oc = 0; oc < 64; oc++) {
        float a = sb[oc];
#pragma unroll
        for (int t = 0; t < 16; t++) a += iv[t] * sw[oc * 16 + t];
        ob[oc * 16384] = fmaxf(a, 0.f);
    }
}

// ---------------- conv2: [16,64,128,128] -> relu -> [16,128,64,64], k4 s2 p1 ----
// block 64 = 16 xg (4px) x 4 rows; 16oc x 4px per thread; cp.async double buffer
__global__ __launch_bounds__(64) void k_conv2(const float* __restrict__ w,
                                              const float* __restrict__ b) {
    // grid (16 oy-tiles, 8 ocg, 16 batch)
    const int oy0 = blockIdx.x * 4, ocb = blockIdx.y * 16, bb = blockIdx.z;
    const int tid = threadIdx.x, txx = tid & 15, tyy = tid >> 4;

    __shared__ __align__(16) float  s_in[2][2][10][136]; // interior at [4..131]
    __shared__ __align__(16) float4 s_w [2][16][2][4];

    // constant-zero halos (cp.async never writes them)
    for (int i = tid; i < 2 * 2 * 10; i += 64) {
        const int bf = i / 20, r = i % 20, ci = r / 10, row = r % 10;
        s_in[bf][ci][row][3]   = 0.f;
        s_in[bf][ci][row][132] = 0.f;
    }

    const float* inb = g_h1 + bb * 64 * 16384;

    auto stage = [&](int it, int bf) {
        const int c0 = it * 2;
        for (int i = tid; i < 640; i += 64) {   // 2ci x 10row x 32 seg
            const int ci = i / 320, r = i % 320, row = r / 32, seg = r % 32;
            const int iy = 2 * oy0 - 1 + row;
            float* dst = &s_in[bf][ci][row][4 + seg * 4];
            if (iy >= 0 && iy < 128)
                __pipeline_memcpy_async(dst, inb + (c0 + ci) * 16384 + iy * 128 + seg * 4, 16);
            else
                *(float4*)dst = make_float4(0.f, 0.f, 0.f, 0.f);
        }
        for (int i = tid; i < 128; i += 64) {   // 16oc x 2ci x 4kh
            const int o = i >> 3, ci = (i >> 2) & 1, kh = i & 3;
            __pipeline_memcpy_async(&s_w[bf][o][ci][kh],
                                    (const float4*)w + ((ocb + o) * 64 + c0 + ci) * 4 + kh, 16);
        }
    };

    float4 acc[16];
#pragma unroll
    for (int o = 0; o < 16; o++) {
        const float bv = b[ocb + o];
        acc[o] = make_float4(bv, bv, bv, bv);
    }

    stage(0, 0);
    __pipeline_commit();
    int cur = 0;
    for (int it = 0; it < 32; it++) {
        __pipeline_wait_prior(0);
        __syncthreads();
        if (it + 1 < 32) { stage(it + 1, cur ^ 1); __pipeline_commit(); }
#pragma unroll
        for (int ci = 0; ci < 2; ci++) {
#pragma unroll
            for (int kh = 0; kh < 4; kh++) {
                const float* rp = &s_in[cur][ci][2 * tyy + kh][8 * txx];
                const float4 P = *(const float4*)rp;
                const float4 Q = *(const float4*)(rp + 4);
                const float4 R = *(const float4*)(rp + 8);
                const float  S = rp[12];
#pragma unroll
                for (int o = 0; o < 16; o++) {
                    const float4 wv = s_w[cur][o][ci][kh];
                    acc[o].x += P.w * wv.x + Q.x * wv.y + Q.y * wv.z + Q.z * wv.w;
                    acc[o].y += Q.y * wv.x + Q.z * wv.y + Q.w * wv.z + R.x * wv.w;
                    acc[o].z += Q.w * wv.x + R.x * wv.y + R.y * wv.z + R.z * wv.w;
                    acc[o].w += R.y * wv.x + R.z * wv.y + R.w * wv.z + S   * wv.w;
                }
            }
        }
        cur ^= 1;
    }
    float* ob = g_h2 + (bb * 128 + ocb) * 4096 + (oy0 + tyy) * 64 + 4 * txx;
#pragma unroll
    for (int o = 0; o < 16; o++) {
        float4 v = acc[o];
        v.x = fmaxf(v.x, 0.f); v.y = fmaxf(v.y, 0.f);
        v.z = fmaxf(v.z, 0.f); v.w = fmaxf(v.w, 0.f);
        *(float4*)(ob + o * 4096) = v;
    }
}

// ------- generic 3x3 s1 p1 conv on 64x64, pre-activated input, cp.async DB ------
// block 128 = 16 xg (4px) x 8 rows; 16oc x 4px per thread
template <bool ADD_BIAS, bool WRITE_RELU>
__global__ __launch_bounds__(128) void k_c3(
    const float* __restrict__ in, const float4* __restrict__ wp,
    const float* __restrict__ bias, float* __restrict__ out,
    float* __restrict__ outr, int COUT, int CIN_TOTAL, int CI_COUNT, int NSPLIT) {
    // grid (8 oy-tiles, COUT/16, 16*NSPLIT)
    const int oy0 = blockIdx.x * 8, ocb = blockIdx.y * 16;
    const int half = blockIdx.z % NSPLIT, bb = blockIdx.z / NSPLIT;
    const int ci0 = half * CI_COUNT;
    const int tid = threadIdx.x, txx = tid & 15, tyy = tid >> 4;

    __shared__ __align__(16) float  s_in[2][4][10][72];  // interior at [4..67]
    __shared__ __align__(16) float4 s_w [2][16][4][3];

    for (int i = tid; i < 2 * 4 * 10; i += 128) {
        const int bf = i / 40, r = i % 40, ci = r / 10, row = r % 10;
        s_in[bf][ci][row][3]  = 0.f;
        s_in[bf][ci][row][68] = 0.f;
    }

    const float* inb = in + bb * CIN_TOTAL * 4096;

    auto stage = [&](int it, int bf) {
        const int c0 = ci0 + it * 4;
        for (int i = tid; i < 640; i += 128) {  // 4ci x 10row x 16 seg
            const int ci = i / 160, r = i % 160, row = r / 16, seg = r % 16;
            const int iy = oy0 - 1 + row;
            float* dst = &s_in[bf][ci][row][4 + seg * 4];
            if (iy >= 0 && iy < 64)
                __pipeline_memcpy_async(dst, inb + (c0 + ci) * 4096 + iy * 64 + seg * 4, 16);
            else
                *(float4*)dst = make_float4(0.f, 0.f, 0.f, 0.f);
        }
        for (int i = tid; i < 192; i += 128) {  // 16oc x 4ci x 3kh
            const int o = i / 12, r = i % 12, ci = r / 3, kh = r % 3;
            __pipeline_memcpy_async(&s_w[bf][o][ci][kh],
                                    &wp[((ocb + o) * CIN_TOTAL + c0 + ci) * 3 + kh], 16);
        }
    };

    float4 acc[16];
#pragma unroll
    for (int o = 0; o < 16; o++) {
        const float bv = ADD_BIAS ? bias[ocb + o] : 0.f;
        acc[o] = make_float4(bv, bv, bv, bv);
    }

    const int NITER = CI_COUNT / 4;
    stage(0, 0);
    __pipeline_commit();
    int cur = 0;
    for (int it = 0; it < NITER; it++) {
        __pipeline_wait_prior(0);
        __syncthreads();
        if (it + 1 < NITER) { stage(it + 1, cur ^ 1); __pipeline_commit(); }
#pragma unroll
        for (int ci = 0; ci < 4; ci++) {
#pragma unroll
            for (int kh = 0; kh < 3; kh++) {
                const float* rp = &s_in[cur][ci][tyy + kh][4 * txx];
                const float4 P = *(const float4*)rp;
                const float4 Q = *(const float4*)(rp + 4);
                const float  Rv = rp[8];
#pragma unroll
                for (int o = 0; o < 16; o++) {
                    const float4 wv = s_w[cur][o][ci][kh];
                    acc[o].x += P.w * wv.x + Q.x * wv.y + Q.y * wv.z;
                    acc[o].y += Q.x * wv.x + Q.y * wv.y + Q.z * wv.z;
                    acc[o].z += Q.y * wv.x + Q.z * wv.y + Q.w * wv.z;
                    acc[o].w += Q.z * wv.x + Q.w * wv.y + Rv  * wv.z;
                }
            }
        }
        cur ^= 1;
    }
    const int off = ((half * 16 + bb) * COUT + ocb) * 4096 + (oy0 + tyy) * 64 + 4 * txx;
#pragma unroll
    for (int o = 0; o < 16; o++) {
        *(float4*)(out + off + o * 4096) = acc[o];
        if (WRITE_RELU) {
            float4 v = acc[o];
            v.x = fmaxf(v.x, 0.f); v.y = fmaxf(v.y, 0.f);
            v.z = fmaxf(v.z, 0.f); v.w = fmaxf(v.w, 0.f);
            *(float4*)(outr + off + o * 4096) = v;
        }
    }
}

// ------- residual 1x1: h3 += b1x1 + W(32->64oc) * relu(t0+t1+bt); h3r = relu ----
__global__ void k_res1x1_add(const float* __restrict__ w, const float* __restrict__ b,
                             const float* __restrict__ bt) {
    // grid (xyg=64, ocg=2, b=16), block 64
    const int xy0 = blockIdx.x * 64, ocb = blockIdx.y * 64, bb = blockIdx.z, tx = threadIdx.x;
    __shared__ float  s_t[32][64];
    __shared__ float4 s_w4[64][8];

    const float* t0 = g_t + bb * 32 * 4096 + xy0;
    const float* t1 = g_t + (16 + bb) * 32 * 4096 + xy0;
    for (int i = tx; i < 32 * 64; i += 64) {
        const int ci = i / 64, xx = i % 64;
        s_t[ci][xx] = fmaxf(t0[ci * 4096 + xx] + t1[ci * 4096 + xx] + bt[ci], 0.f);
    }
    for (int i = tx; i < 64 * 32; i += 64) {
        const int o = i / 32, ci = i % 32;
        ((float*)&s_w4[o][0])[ci] = w[(ocb + o) * 32 + ci];
    }
    __syncthreads();

    float acc[64];
#pragma unroll
    for (int o = 0; o < 64; o++) acc[o] = b[ocb + o];
    for (int cq = 0; cq < 8; cq++) {
        const float v0 = s_t[cq * 4 + 0][tx];
        const float v1 = s_t[cq * 4 + 1][tx];
        const float v2 = s_t[cq * 4 + 2][tx];
        const float v3 = s_t[cq * 4 + 3][tx];
#pragma unroll
        for (int o = 0; o < 64; o++) {
            const float4 wv = s_w4[o][cq];
            acc[o] += v0 * wv.x + v1 * wv.y + v2 * wv.z + v3 * wv.w;
        }
    }
    float* hb  = g_h3  + (bb * 128 + ocb) * 4096 + xy0 + tx;
    float* hrb = g_h3r + (bb * 128 + ocb) * 4096 + xy0 + tx;
#pragma unroll
    for (int o = 0; o < 64; o++) {
        const float hv = hb[o * 4096] + acc[o];
        hb[o * 4096]  = hv;
        hrb[o * 4096] = fmaxf(hv, 0.f);
    }
}

// ------- pre-VQ 1x1: z[pos][4] = W(128->4) * h3r + bias -------------------------
__global__ void k_z(const float* __restrict__ w, const float* __restrict__ b) {
    const int xy0 = blockIdx.x * 64, bb = blockIdx.y, tx = threadIdx.x;
    __shared__ float s_h[128][64];
    __shared__ float s_w[4][128];

    const float* hb = g_h3r + bb * 128 * 4096 + xy0;
    for (int i = tx; i < 128 * 64; i += 64) {
        const int ci = i / 64, xx = i % 64;
        s_h[ci][xx] = hb[ci * 4096 + xx];
    }
    for (int i = tx; i < 512; i += 64) s_w[i / 128][i % 128] = w[i];
    __syncthreads();

    float a0 = b[0], a1 = b[1], a2 = b[2], a3 = b[3];
#pragma unroll 4
    for (int ci = 0; ci < 128; ci++) {
        const float hv = s_h[ci][tx];
        a0 += hv * s_w[0][ci];
        a1 += hv * s_w[1][ci];
        a2 += hv * s_w[2][ci];
        a3 += hv * s_w[3][ci];
    }
    ((float4*)g_z)[bb * 4096 + xy0 + tx] = make_float4(a0, a1, a2, a3);
}

// ------- cosine VQ: argmax_k <z, e_k/||e_k||>, gather codebook ------------------
// Reference also normalizes z; positive scalar can't change argmax -> skipped.
__global__ void k_vq(const float* __restrict__ cb, float* __restrict__ out) {
    // grid (posg=8, b=16), block 256; 2 positions per thread
    const int bb = blockIdx.y;
    const int p0 = (blockIdx.x * 256 + threadIdx.x) * 2;
    __shared__ float4 s_en[2048];
    for (int k = threadIdx.x; k < 2048; k += 256) {
        const float4 c = ((const float4*)cb)[k];
        const float n = sqrtf(c.x * c.x + c.y * c.y + c.z * c.z + c.w * c.w);
        const float inv = 1.f / (n + 1e-12f);
        s_en[k] = make_float4(c.x * inv, c.y * inv, c.z * inv, c.w * inv);
    }
    __syncthreads();

    float4 z[2];
#pragma unroll
    for (int q = 0; q < 2; q++) z[q] = ((const float4*)g_z)[bb * 4096 + p0 + q];

    float best[2] = {-1e30f, -1e30f};
    int bi[2] = {0, 0};
#pragma unroll 4
    for (int k = 0; k < 2048; k++) {
        const float4 e = s_en[k];
#pragma unroll
        for (int q = 0; q < 2; q++) {
            const float s = z[q].x * e.x + z[q].y * e.y + z[q].z * e.z + z[q].w * e.w;
            if (s > best[q]) { best[q] = s; bi[q] = k; }  // strict >: first max (JAX)
        }
    }
    const float4 q0 = ((const float4*)cb)[bi[0]];
    const float4 q1 = ((const float4*)cb)[bi[1]];
    float* ob = out + bb * 4 * 4096 + p0;
    *(float2*)(ob)            = make_float2(q0.x, q1.x);
    *(float2*)(ob + 4096)     = make_float2(q0.y, q1.y);
    *(float2*)(ob + 2 * 4096) = make_float2(q0.z, q1.z);
    *(float2*)(ob + 3 * 4096) = make_float2(q0.w, q1.w);
}

// --------------------------------- launcher -------------------------------------
extern "C" void kernel_launch(void* const* d_in, const int* in_sizes, int n_in,
                              void* d_out, int out_size) {
    const float* cond  = (const float*)d_in[0];
    const float* w1    = (const float*)d_in[1];
    const float* b1    = (const float*)d_in[2];
    const float* w2    = (const float*)d_in[3];
    const float* b2    = (const float*)d_in[4];
    const float* w3    = (const float*)d_in[5];
    const float* b3    = (const float*)d_in[6];
    const float* r1w1  = (const float*)d_in[7];
    const float* r1b1  = (const float*)d_in[8];
    const float* r1w2  = (const float*)d_in[9];
    const float* r1b2  = (const float*)d_in[10];
    const float* r2w1  = (const float*)d_in[11];
    const float* r2b1  = (const float*)d_in[12];
    const float* r2w2  = (const float*)d_in[13];
    const float* r2b2  = (const float*)d_in[14];
    const float* wpre  = (const float*)d_in[15];
    const float* bpre  = (const float*)d_in[16];
    const float* cbk   = (const float*)d_in[17];

    float *h2p, *h3p, *h3rp, *tp;
    float4 *w3pp, *wr1pp, *wr2pp;
    cudaGetSymbolAddress((void**)&h2p,   g_h2);
    cudaGetSymbolAddress((void**)&h3p,   g_h3);
    cudaGetSymbolAddress((void**)&h3rp,  g_h3r);
    cudaGetSymbolAddress((void**)&tp,    g_t);
    cudaGetSymbolAddress((void**)&w3pp,  g_w3p);
    cudaGetSymbolAddress((void**)&wr1pp, g_wr1p);
    cudaGetSymbolAddress((void**)&wr2pp, g_wr2p);

    k_padw<<<288, 256>>>(w3, r1w1, r2w1);
    k_conv1<<<dim3(128, 16), 128>>>(cond, w1, b1);
    k_conv2<<<dim3(16, 8, 16), 64>>>(w2, b2);
    k_c3<true, true><<<dim3(8, 8, 16), 128>>>(h2p, w3pp, b3, h3p, h3rp, 128, 128, 128, 1);

    k_c3<false, false><<<dim3(8, 2, 32), 128>>>(h3rp, wr1pp, nullptr, tp, nullptr, 32, 128, 64, 2);
    k_res1x1_add<<<dim3(64, 2, 16), 64>>>(r1w2, r1b2, r1b1);

    k_c3<false, false><<<dim3(8, 2, 32), 128>>>(h3rp, wr2pp, nullptr, tp, nullptr, 32, 128, 64, 2);
    k_res1x1_add<<<dim3(64, 2, 16), 64>>>(r2w2, r2b2, r2b1);

    k_z<<<dim3(64, 16), 64>>>(wpre, bpre);
    k_vq<<<dim3(8, 16), 256>>>(cbk, (float*)d_out);
}